// round 2
// baseline (speedup 1.0000x reference)
#include <cuda_runtime.h>
#include <cstdint>

#define T_DIM 2048
#define H_DIM 1024
#define I_DIM 1408
#define E_DIM 8
#define K_TOP 2
#define CAP   1024
#define TWO_I 2816

// ---------------- scratch (device globals; no allocation allowed) ----------
__device__ int   d_pos[T_DIM * K_TOP];
__device__ int   d_cnt[E_DIM];
__device__ int   d_slot[E_DIM * CAP];                       // (e,pos) -> flat slot idx
__device__ float d_h[(size_t)E_DIM * CAP * TWO_I];          // pre-activation, 92 MB
__device__ float d_y[(size_t)E_DIM * CAP * H_DIM];          // expert output, 33 MB

// ---------------- helpers ---------------------------------------------------
__device__ __forceinline__ unsigned f2tf32(float x) {
    unsigned r;
    asm("cvt.rna.tf32.f32 %0, %1;" : "=r"(r) : "f"(x));
    return r;
}

__device__ __forceinline__ void mma_tf32(float* c, const unsigned* a, const unsigned* b) {
    asm volatile(
        "mma.sync.aligned.m16n8k8.row.col.f32.tf32.tf32.f32 "
        "{%0,%1,%2,%3}, {%4,%5,%6,%7}, {%8,%9}, {%0,%1,%2,%3};"
        : "+f"(c[0]), "+f"(c[1]), "+f"(c[2]), "+f"(c[3])
        : "r"(a[0]), "r"(a[1]), "r"(a[2]), "r"(a[3]),
          "r"(b[0]), "r"(b[1]));
}

// ---------------- 1. routing ------------------------------------------------
// Exact reference semantics: pos[i] = #{j<i : ids[j]==ids[i]} (flat order),
// keep = pos < CAP. 256 threads x 16 elements each.
__global__ void route_kernel(const int* __restrict__ ids) {
    __shared__ int s_cnt[256][8];
    int tid = threadIdx.x;
    int local[8];
#pragma unroll
    for (int e = 0; e < 8; e++) local[e] = 0;
    int base = tid * 16;
#pragma unroll
    for (int i = 0; i < 16; i++) {
        int e = ids[base + i];
#pragma unroll
        for (int q = 0; q < 8; q++) if (q == e) local[q]++;
    }
#pragma unroll
    for (int e = 0; e < 8; e++) s_cnt[tid][e] = local[e];
    __syncthreads();
    if (tid < 8) {
        int acc = 0;
        for (int i = 0; i < 256; i++) {
            int v = s_cnt[i][tid];
            s_cnt[i][tid] = acc;
            acc += v;
        }
        d_cnt[tid] = acc;
    }
    __syncthreads();
    int run[8];
#pragma unroll
    for (int e = 0; e < 8; e++) run[e] = s_cnt[tid][e];
    for (int i = 0; i < 16; i++) {
        int idx = base + i;
        int e = ids[idx];
        int p = 0;
#pragma unroll
        for (int q = 0; q < 8; q++) if (q == e) p = run[q]++;
        d_pos[idx] = p;
        if (p < CAP) d_slot[e * CAP + p] = idx;
    }
}

// ---------------- GEMM core params -----------------------------------------
// BM=128, BN=128, BK=32. 256 threads = 8 warps, 2 (M) x 4 (N).
// Warp tile 64x32 -> 4x4 m16n8k8 fragments.

// ---------------- 2. GEMM1: h = gather(x) @ w1^T ---------------------------
__global__ __launch_bounds__(256) void gemm1_kernel(const float* __restrict__ hidden,
                                                    const float* __restrict__ w1) {
    const int e = blockIdx.z, mt = blockIdx.y, nt = blockIdx.x;
    const int cnt = d_cnt[e];
    const int m0 = mt * 128;
    if (m0 >= cnt) return;

    __shared__ float As[128][36];
    __shared__ float Bs[128][36];

    const int tid = threadIdx.x;
    const int lane = tid & 31, warp = tid >> 5;
    const int wm = warp & 1, wn = warp >> 1;
    const int g = lane >> 2, t = lane & 3;

    float acc[4][4][4];
#pragma unroll
    for (int mf = 0; mf < 4; mf++)
#pragma unroll
        for (int nf = 0; nf < 4; nf++)
#pragma unroll
            for (int q = 0; q < 4; q++) acc[mf][nf][q] = 0.f;

    // per-thread A-row gather info (row = (tid + i*256)>>3)
    int atok[4]; bool aval[4];
#pragma unroll
    for (int i = 0; i < 4; i++) {
        int r = (tid + i * 256) >> 3;
        int m = m0 + r;
        aval[i] = (m < cnt);
        atok[i] = aval[i] ? (d_slot[e * CAP + m] / K_TOP) : 0;
    }
    const float* wptr = w1 + ((size_t)e * TWO_I + (size_t)nt * 128) * H_DIM;

    for (int kc = 0; kc < H_DIM; kc += 32) {
#pragma unroll
        for (int i = 0; i < 4; i++) {
            int f4 = tid + i * 256;
            int r = f4 >> 3, c = (f4 & 7) * 4;
            float4 v = make_float4(0.f, 0.f, 0.f, 0.f);
            if (aval[i]) v = *(const float4*)(hidden + (size_t)atok[i] * H_DIM + kc + c);
            As[r][c + 0] = __uint_as_float(f2tf32(v.x));
            As[r][c + 1] = __uint_as_float(f2tf32(v.y));
            As[r][c + 2] = __uint_as_float(f2tf32(v.z));
            As[r][c + 3] = __uint_as_float(f2tf32(v.w));
        }
#pragma unroll
        for (int i = 0; i < 4; i++) {
            int f4 = tid + i * 256;
            int r = f4 >> 3, c = (f4 & 7) * 4;
            float4 v = *(const float4*)(wptr + (size_t)r * H_DIM + kc + c);
            Bs[r][c + 0] = __uint_as_float(f2tf32(v.x));
            Bs[r][c + 1] = __uint_as_float(f2tf32(v.y));
            Bs[r][c + 2] = __uint_as_float(f2tf32(v.z));
            Bs[r][c + 3] = __uint_as_float(f2tf32(v.w));
        }
        __syncthreads();
#pragma unroll
        for (int kk = 0; kk < 32; kk += 8) {
            unsigned a[4][4], b[4][2];
#pragma unroll
            for (int mf = 0; mf < 4; mf++) {
                int r = wm * 64 + mf * 16;
                a[mf][0] = __float_as_uint(As[r + g][kk + t]);
                a[mf][1] = __float_as_uint(As[r + g + 8][kk + t]);
                a[mf][2] = __float_as_uint(As[r + g][kk + t + 4]);
                a[mf][3] = __float_as_uint(As[r + g + 8][kk + t + 4]);
            }
#pragma unroll
            for (int nf = 0; nf < 4; nf++) {
                int r = wn * 32 + nf * 8;
                b[nf][0] = __float_as_uint(Bs[r + g][kk + t]);
                b[nf][1] = __float_as_uint(Bs[r + g][kk + t + 4]);
            }
#pragma unroll
            for (int mf = 0; mf < 4; mf++)
#pragma unroll
                for (int nf = 0; nf < 4; nf++) mma_tf32(acc[mf][nf], a[mf], b[nf]);
        }
        __syncthreads();
    }

    // epilogue -> d_h
#pragma unroll
    for (int mf = 0; mf < 4; mf++) {
        int mlo = m0 + wm * 64 + mf * 16 + g;
        int mhi = mlo + 8;
#pragma unroll
        for (int nf = 0; nf < 4; nf++) {
            int col = nt * 128 + wn * 32 + nf * 8 + 2 * t;
            if (mlo < cnt) {
                float* dst = d_h + ((size_t)e * CAP + mlo) * TWO_I + col;
                dst[0] = acc[mf][nf][0];
                dst[1] = acc[mf][nf][1];
            }
            if (mhi < cnt) {
                float* dst = d_h + ((size_t)e * CAP + mhi) * TWO_I + col;
                dst[0] = acc[mf][nf][2];
                dst[1] = acc[mf][nf][3];
            }
        }
    }
}

// ---------------- 3. GEMM2: y = (silu(gate)*up) @ w2^T ---------------------
__global__ __launch_bounds__(256) void gemm2_kernel(const float* __restrict__ w2) {
    const int e = blockIdx.z, mt = blockIdx.y, nt = blockIdx.x;
    const int cnt = d_cnt[e];
    const int m0 = mt * 128;
    if (m0 >= cnt) return;

    __shared__ float As[128][36];
    __shared__ float Bs[128][36];

    const int tid = threadIdx.x;
    const int lane = tid & 31, warp = tid >> 5;
    const int wm = warp & 1, wn = warp >> 1;
    const int g = lane >> 2, t = lane & 3;

    float acc[4][4][4];
#pragma unroll
    for (int mf = 0; mf < 4; mf++)
#pragma unroll
        for (int nf = 0; nf < 4; nf++)
#pragma unroll
            for (int q = 0; q < 4; q++) acc[mf][nf][q] = 0.f;

    const float* wptr = w2 + ((size_t)e * H_DIM + (size_t)nt * 128) * I_DIM;

    for (int kc = 0; kc < I_DIM; kc += 32) {
#pragma unroll
        for (int i = 0; i < 4; i++) {
            int f4 = tid + i * 256;
            int r = f4 >> 3, c = (f4 & 7) * 4;
            int m = m0 + r;
            float4 av = make_float4(0.f, 0.f, 0.f, 0.f);
            if (m < cnt) {
                const float* hrow = d_h + ((size_t)e * CAP + m) * TWO_I + kc + c;
                float4 gv = *(const float4*)(hrow);
                float4 uv = *(const float4*)(hrow + I_DIM);
                av.x = gv.x * uv.x / (1.f + __expf(-gv.x));
                av.y = gv.y * uv.y / (1.f + __expf(-gv.y));
                av.z = gv.z * uv.z / (1.f + __expf(-gv.z));
                av.w = gv.w * uv.w / (1.f + __expf(-gv.w));
            }
            As[r][c + 0] = __uint_as_float(f2tf32(av.x));
            As[r][c + 1] = __uint_as_float(f2tf32(av.y));
            As[r][c + 2] = __uint_as_float(f2tf32(av.z));
            As[r][c + 3] = __uint_as_float(f2tf32(av.w));
        }
#pragma unroll
        for (int i = 0; i < 4; i++) {
            int f4 = tid + i * 256;
            int r = f4 >> 3, c = (f4 & 7) * 4;
            float4 v = *(const float4*)(wptr + (size_t)r * I_DIM + kc + c);
            Bs[r][c + 0] = __uint_as_float(f2tf32(v.x));
            Bs[r][c + 1] = __uint_as_float(f2tf32(v.y));
            Bs[r][c + 2] = __uint_as_float(f2tf32(v.z));
            Bs[r][c + 3] = __uint_as_float(f2tf32(v.w));
        }
        __syncthreads();
#pragma unroll
        for (int kk = 0; kk < 32; kk += 8) {
            unsigned a[4][4], b[4][2];
#pragma unroll
            for (int mf = 0; mf < 4; mf++) {
                int r = wm * 64 + mf * 16;
                a[mf][0] = __float_as_uint(As[r + g][kk + t]);
                a[mf][1] = __float_as_uint(As[r + g + 8][kk + t]);
                a[mf][2] = __float_as_uint(As[r + g][kk + t + 4]);
                a[mf][3] = __float_as_uint(As[r + g + 8][kk + t + 4]);
            }
#pragma unroll
            for (int nf = 0; nf < 4; nf++) {
                int r = wn * 32 + nf * 8;
                b[nf][0] = __float_as_uint(Bs[r + g][kk + t]);
                b[nf][1] = __float_as_uint(Bs[r + g][kk + t + 4]);
            }
#pragma unroll
            for (int mf = 0; mf < 4; mf++)
#pragma unroll
                for (int nf = 0; nf < 4; nf++) mma_tf32(acc[mf][nf], a[mf], b[nf]);
        }
        __syncthreads();
    }

#pragma unroll
    for (int mf = 0; mf < 4; mf++) {
        int mlo = m0 + wm * 64 + mf * 16 + g;
        int mhi = mlo + 8;
#pragma unroll
        for (int nf = 0; nf < 4; nf++) {
            int col = nt * 128 + wn * 32 + nf * 8 + 2 * t;
            if (mlo < cnt) {
                float* dst = d_y + ((size_t)e * CAP + mlo) * H_DIM + col;
                dst[0] = acc[mf][nf][0];
                dst[1] = acc[mf][nf][1];
            }
            if (mhi < cnt) {
                float* dst = d_y + ((size_t)e * CAP + mhi) * H_DIM + col;
                dst[0] = acc[mf][nf][2];
                dst[1] = acc[mf][nf][3];
            }
        }
    }
}

// ---------------- 4. combine ------------------------------------------------
__global__ void combine_kernel(const float* __restrict__ tw,
                               const int* __restrict__ ids,
                               float* __restrict__ out) {
    int tok = blockIdx.x;  // 0..T-1
    int e0 = ids[tok * 2 + 0], e1 = ids[tok * 2 + 1];
    int p0 = d_pos[tok * 2 + 0], p1 = d_pos[tok * 2 + 1];
    float w0 = tw[tok * 2 + 0], w1v = tw[tok * 2 + 1];
    bool k0 = (p0 < CAP), k1 = (p1 < CAP);

    int c = threadIdx.x;  // 256 threads, one float4 each: H=1024
    float4 r = make_float4(0.f, 0.f, 0.f, 0.f);
    if (k0) {
        float4 v = *(const float4*)(d_y + ((size_t)e0 * CAP + p0) * H_DIM + c * 4);
        r.x += w0 * v.x; r.y += w0 * v.y; r.z += w0 * v.z; r.w += w0 * v.w;
    }
    if (k1) {
        float4 v = *(const float4*)(d_y + ((size_t)e1 * CAP + p1) * H_DIM + c * 4);
        r.x += w1v * v.x; r.y += w1v * v.y; r.z += w1v * v.z; r.w += w1v * v.w;
    }
    *(float4*)(out + (size_t)tok * H_DIM + c * 4) = r;
}

// ---------------- launch -----------------------------------------------------
extern "C" void kernel_launch(void* const* d_in, const int* in_sizes, int n_in,
                              void* d_out, int out_size) {
    const float* hidden = (const float*)d_in[0];
    const float* w1     = (const float*)d_in[1];
    const float* w2     = (const float*)d_in[2];
    const float* tw     = (const float*)d_in[3];
    const int*   ids    = (const int*)d_in[4];
    float* out = (float*)d_out;

    route_kernel<<<1, 256>>>(ids);
    gemm1_kernel<<<dim3(TWO_I / 128, CAP / 128, E_DIM), 256>>>(hidden, w1);
    gemm2_kernel<<<dim3(H_DIM / 128, CAP / 128, E_DIM), 256>>>(w2);
    combine_kernel<<<T_DIM, 256>>>(tw, ids, out);
}